// round 1
// baseline (speedup 1.0000x reference)
#include <cuda_runtime.h>
#include <math.h>

// ---- problem constants ----
#define NB    4
#define LL    512
#define NNODE 2048          // NB*LL
#define D0V   640
#define PV    128
#define CV    32
#define HV    4
#define NLV   3
#define RADIN 130
#define HIDV  64
#define R4C   128
#define EMAX  262144

// ---- device scratch (static, allocation-free) ----
__device__ float    g_h0  [NNODE*CV];
__device__ float    g_h1  [NNODE*CV*3];
__device__ float    g_q   [NNODE*CV];
__device__ float    g_a00 [NNODE*CV];
__device__ float    g_a10 [NNODE*CV];
__device__ float    g_g01 [NNODE*CV*3];
__device__ float    g_g11 [NNODE*CV*3];
__device__ float    g_ef  [(size_t)EMAX*RADIN];
__device__ float    g_rhat[(size_t)EMAX*3];
__device__ float    g_k   [(size_t)EMAX*CV];
__device__ float    g_s10 [(size_t)EMAX*CV];
__device__ float    g_w11e[(size_t)EMAX*CV];
__device__ float    g_logit[(size_t)EMAX*HV];
__device__ float    g_aexp [(size_t)EMAX*HV];
__device__ unsigned g_mx  [NNODE*HV];
__device__ float    g_den [NNODE*HV];
__device__ float    g_agg0[NNODE*CV];
__device__ float    g_agg1[NNODE*CV*3];

// order-preserving float<->uint for atomicMax
__device__ __forceinline__ unsigned fenc(float f){
    unsigned u = __float_as_uint(f);
    return (u & 0x80000000u) ? ~u : (u | 0x80000000u);
}
__device__ __forceinline__ float fdec(unsigned u){
    return __uint_as_float((u & 0x80000000u) ? (u & 0x7fffffffu) : ~u);
}
__device__ __forceinline__ float warpsum(float v){
    #pragma unroll
    for (int o = 16; o; o >>= 1) v += __shfl_xor_sync(0xffffffffu, v, o);
    return v;
}

// ---- K0: h0 = seq @ Win0 ; h1[n,c,d] = x[n,d]*Win1[c] ----
__global__ void k_init_nodes(const float* __restrict__ seq,
                             const float* __restrict__ coords,
                             const float* __restrict__ Win0,
                             const float* __restrict__ Win1){
    int n = blockIdx.x, t = threadIdx.x;
    __shared__ float s[D0V];
    __shared__ float red[128];
    for (int i = t; i < D0V; i += 128) s[i] = seq[(size_t)n*D0V + i];
    __syncthreads();
    int f = t & 31, part = t >> 5;
    float acc = 0.f;
    for (int i = part*160; i < (part+1)*160; i++) acc += s[i]*Win0[i*CV + f];
    red[t] = acc;
    __syncthreads();
    if (part == 0){
        float v = red[f] + red[f+32] + red[f+64] + red[f+96];
        g_h0[n*CV + f] = v;
        float w = Win1[f];
        float x0 = coords[n*3+0], x1 = coords[n*3+1], x2 = coords[n*3+2];
        g_h1[(n*CV+f)*3+0] = x0*w;
        g_h1[(n*CV+f)*3+1] = x1*w;
        g_h1[(n*CV+f)*3+2] = x2*w;
    }
}

// ---- K1: per-edge geometry + ef = [pair(128), bppm, r] ----
__global__ void k_edge_setup(const float* __restrict__ coords,
                             const float* __restrict__ pair,
                             const float* __restrict__ bppm,
                             const int* __restrict__ src,
                             const int* __restrict__ dst, int E){
    int e = blockIdx.x*8 + (threadIdx.x >> 5);
    if (e >= E) return;
    int lane = threadIdx.x & 31;
    int s = src[e], d = dst[e];
    float rx = coords[d*3+0] - coords[s*3+0];
    float ry = coords[d*3+1] - coords[s*3+1];
    float rz = coords[d*3+2] - coords[s*3+2];
    float r  = sqrtf(rx*rx + ry*ry + rz*rz + 1e-12f);
    float inv = 1.f/(r + 1e-8f);
    if (lane == 0){
        g_rhat[(size_t)e*3+0] = rx*inv;
        g_rhat[(size_t)e*3+1] = ry*inv;
        g_rhat[(size_t)e*3+2] = rz*inv;
    }
    int di = d % LL;
    const float* pr = pair + ((size_t)s*LL + di)*PV;
    float* ef = g_ef + (size_t)e*RADIN;
    for (int i = lane; i < PV; i += 32) ef[i] = pr[i];
    if (lane == 0){
        ef[PV]   = bppm[(size_t)s*LL + di];
        ef[PV+1] = r;
    }
}

// ---- zero per-layer accumulators ----
__global__ void k_layer_zero(){
    int i = blockIdx.x*256 + threadIdx.x;
    if (i < NNODE*HV){ g_mx[i] = 0x007FFFFFu; g_den[i] = 0.f; }  // enc(-inf)
    if (i < NNODE*CV)   g_agg0[i] = 0.f;
    if (i < NNODE*CV*3) g_agg1[i] = 0.f;
}

// ---- K2: per-node precompute q, a00, a10, g01, g11 ----
__global__ void k_node_pre(const float* __restrict__ Wq,
                           const float* __restrict__ Wm00,
                           const float* __restrict__ Wm10,
                           const float* __restrict__ Wm01,
                           const float* __restrict__ Wm11){
    int n = blockIdx.x, f = threadIdx.x;
    __shared__ float sh0[CV], sh1[CV*3];
    sh0[f] = g_h0[n*CV + f];
    sh1[f*3+0] = g_h1[(n*CV+f)*3+0];
    sh1[f*3+1] = g_h1[(n*CV+f)*3+1];
    sh1[f*3+2] = g_h1[(n*CV+f)*3+2];
    __syncwarp();
    float q=0, a00=0, a10=0;
    float g01x=0, g01y=0, g01z=0, g11x=0, g11y=0, g11z=0;
    #pragma unroll 4
    for (int c = 0; c < CV; c++){
        float h = sh0[c];
        q   += h*Wq  [c*CV+f];
        a00 += h*Wm00[c*CV+f];
        a10 += h*Wm10[c*CV+f];
        float w01 = Wm01[c*CV+f], w11 = Wm11[c*CV+f];
        float hx = sh1[c*3+0], hy = sh1[c*3+1], hz = sh1[c*3+2];
        g01x += hx*w01; g01y += hy*w01; g01z += hz*w01;
        g11x += hx*w11; g11y += hy*w11; g11z += hz*w11;
    }
    g_q  [n*CV+f] = q;
    g_a00[n*CV+f] = a00;
    g_a10[n*CV+f] = a10;
    int b = (n*CV+f)*3;
    g_g01[b+0]=g01x; g_g01[b+1]=g01y; g_g01[b+2]=g01z;
    g_g11[b+0]=g11x; g_g11[b+1]=g11y; g_g11[b+2]=g11z;
}

// ---- K3: radial MLP + messages + logits (+atomicMax) ; 4 edges per warp ----
// smem: Wr1 8320 | br1 64 | Wr2 8192 | br2 128 | ef 8*520 | hid 8*256
#define SMF_WR1 0
#define SMF_BR1 8320
#define SMF_WR2 8384
#define SMF_BR2 16576
#define SMF_EF  16704
#define SMF_HID 20864
#define SMEM_FLOATS 22912
#define SMEM_BYTES (SMEM_FLOATS*4)

__global__ void k_edge_pass1(const int* __restrict__ esrc,
                             const int* __restrict__ edst,
                             const float* __restrict__ Wr1,
                             const float* __restrict__ br1,
                             const float* __restrict__ Wr2,
                             const float* __restrict__ br2, int E){
    extern __shared__ float sm[];
    float* sWr1 = sm + SMF_WR1;
    float* sbr1 = sm + SMF_BR1;
    float* sWr2 = sm + SMF_WR2;
    float* sbr2 = sm + SMF_BR2;
    int tid = threadIdx.x;
    for (int i = tid; i < 8320; i += 256) sWr1[i] = Wr1[i];
    for (int i = tid; i < 64;   i += 256) sbr1[i] = br1[i];
    for (int i = tid; i < 8192; i += 256) sWr2[i] = Wr2[i];
    for (int i = tid; i < 128;  i += 256) sbr2[i] = br2[i];
    __syncthreads();

    int w    = tid >> 5;
    int lane = tid & 31;
    float* myef  = sm + SMF_EF  + w*520;   // 4 edges x 130
    float* myhid = sm + SMF_HID + w*256;   // 4 edges x 64
    int warpGlobal = blockIdx.x*8 + w;
    int nGroups = (E + 3) >> 2;
    int stride  = gridDim.x * 8;

    for (int g = warpGlobal; g < nGroups; g += stride){
        int e0 = g*4;
        // stage ef for 4 edges
        for (int t = lane; t < 520; t += 32){
            int ee = e0 + t/130, ii = t - (t/130)*130;
            myef[t] = (ee < E) ? g_ef[(size_t)ee*RADIN + ii] : 0.f;
        }
        __syncwarp();
        // layer1: 130 -> 64 (2 hidden units/lane, 4 edges)
        float hA0=sbr1[lane], hA1=sbr1[lane+32];
        float hB0=hA0, hB1=hA1, hC0=hA0, hC1=hA1, hD0=hA0, hD1=hA1;
        #pragma unroll 2
        for (int i = 0; i < 130; i++){
            float w0 = sWr1[i*64+lane], w1 = sWr1[i*64+32+lane];
            float eA = myef[i], eB = myef[130+i], eC = myef[260+i], eD = myef[390+i];
            hA0 += eA*w0; hA1 += eA*w1;
            hB0 += eB*w0; hB1 += eB*w1;
            hC0 += eC*w0; hC1 += eC*w1;
            hD0 += eD*w0; hD1 += eD*w1;
        }
        myhid[lane]     = fmaxf(hA0,0.f); myhid[32+lane]  = fmaxf(hA1,0.f);
        myhid[64+lane]  = fmaxf(hB0,0.f); myhid[96+lane]  = fmaxf(hB1,0.f);
        myhid[128+lane] = fmaxf(hC0,0.f); myhid[160+lane] = fmaxf(hC1,0.f);
        myhid[192+lane] = fmaxf(hD0,0.f); myhid[224+lane] = fmaxf(hD1,0.f);
        __syncwarp();
        // layer2: 64 -> 128 (4 quarters/lane, 4 edges)
        float o[4][4];
        #pragma unroll
        for (int ei = 0; ei < 4; ei++)
            #pragma unroll
            for (int m = 0; m < 4; m++) o[ei][m] = sbr2[m*32+lane];
        #pragma unroll 2
        for (int j = 0; j < 64; j++){
            float w0 = sWr2[j*128+lane],    w1 = sWr2[j*128+32+lane];
            float w2 = sWr2[j*128+64+lane], w3 = sWr2[j*128+96+lane];
            float hA = myhid[j], hB = myhid[64+j], hC = myhid[128+j], hD = myhid[192+j];
            o[0][0]+=hA*w0; o[0][1]+=hA*w1; o[0][2]+=hA*w2; o[0][3]+=hA*w3;
            o[1][0]+=hB*w0; o[1][1]+=hB*w1; o[1][2]+=hB*w2; o[1][3]+=hB*w3;
            o[2][0]+=hC*w0; o[2][1]+=hC*w1; o[2][2]+=hC*w2; o[2][3]+=hC*w3;
            o[3][0]+=hD*w0; o[3][1]+=hD*w1; o[3][2]+=hD*w2; o[3][3]+=hD*w3;
        }
        // per-edge tail: k, s10, w11, logit, atomicMax
        #pragma unroll
        for (int ei = 0; ei < 4; ei++){
            int e = e0 + ei;
            if (e < E){
                int s = esrc[e], d = edst[e];
                float rx = g_rhat[(size_t)e*3+0];
                float ry = g_rhat[(size_t)e*3+1];
                float rz = g_rhat[(size_t)e*3+2];
                int sb = (s*CV+lane)*3;
                float gdot = g_g01[sb]*rx + g_g01[sb+1]*ry + g_g01[sb+2]*rz;
                float kc = o[ei][0]*g_a00[s*CV+lane] + o[ei][1]*gdot;
                size_t ec = (size_t)e*CV + lane;
                g_k[ec]    = kc;
                g_s10[ec]  = o[ei][2]*g_a10[s*CV+lane];
                g_w11e[ec] = o[ei][3];
                float p = g_q[d*CV+lane]*kc;
                p += __shfl_down_sync(0xffffffffu, p, 4);
                p += __shfl_down_sync(0xffffffffu, p, 2);
                p += __shfl_down_sync(0xffffffffu, p, 1);
                if ((lane & 7) == 0){
                    float lg = p * 0.3535533906f;   // 1/sqrt(8)
                    g_logit[(size_t)e*HV + (lane>>3)] = lg;
                    atomicMax(&g_mx[d*HV + (lane>>3)], fenc(lg));
                }
            }
        }
    }
}

// ---- K4: a = exp(logit - mx[dst]); den += a ----
__global__ void k_att_norm(const int* __restrict__ edst, int E){
    int i = blockIdx.x*256 + threadIdx.x;
    if (i >= E*HV) return;
    int e = i >> 2, h = i & 3;
    int d = edst[e];
    float mx = fdec(g_mx[d*HV + h]);
    float a = expf(g_logit[i] - mx);
    g_aexp[i] = a;
    atomicAdd(&g_den[d*HV + h], a);
}

// ---- K5: alpha-weighted aggregation into agg0/agg1 ----
__global__ void k_edge_pass3(const int* __restrict__ esrc,
                             const int* __restrict__ edst, int E){
    int e = blockIdx.x*8 + (threadIdx.x >> 5);
    if (e >= E) return;
    int lane = threadIdx.x & 31;
    int h = lane >> 3;
    int s = esrc[e], d = edst[e];
    float alpha = g_aexp[(size_t)e*HV + h] / (g_den[d*HV + h] + 1e-9f);
    size_t ec = (size_t)e*CV + lane;
    float kc = g_k[ec];
    atomicAdd(&g_agg0[d*CV + lane], alpha*kc);
    float w11 = g_w11e[ec], s10 = g_s10[ec];
    float rx = g_rhat[(size_t)e*3+0];
    float ry = g_rhat[(size_t)e*3+1];
    float rz = g_rhat[(size_t)e*3+2];
    int gi = (s*CV+lane)*3;
    float m1x = w11*g_g11[gi+0] + s10*rx;
    float m1y = w11*g_g11[gi+1] + s10*ry;
    float m1z = w11*g_g11[gi+2] + s10*rz;
    int ai = (d*CV+lane)*3;
    atomicAdd(&g_agg1[ai+0], alpha*m1x);
    atomicAdd(&g_agg1[ai+1], alpha*m1y);
    atomicAdd(&g_agg1[ai+2], alpha*m1z);
}

// ---- K6: node update + LayerNorm(deg0) + norm-gate(deg1) ----
__global__ void k_node_update(const float* __restrict__ Wself0,
                              const float* __restrict__ Wself1,
                              const float* __restrict__ gamma0,
                              const float* __restrict__ beta0,
                              const float* __restrict__ gamma1){
    int n = blockIdx.x, f = threadIdx.x;
    __shared__ float sa0[CV], sa1[CV*3];
    sa0[f] = g_agg0[n*CV + f];
    sa1[f]      = g_agg1[n*CV*3 + f];
    sa1[f+32]   = g_agg1[n*CV*3 + f + 32];
    sa1[f+64]   = g_agg1[n*CV*3 + f + 64];
    __syncwarp();
    float nh0 = g_h0[n*CV+f];
    float x = g_h1[(n*CV+f)*3+0];
    float y = g_h1[(n*CV+f)*3+1];
    float z = g_h1[(n*CV+f)*3+2];
    #pragma unroll 4
    for (int c = 0; c < CV; c++){
        float w0 = Wself0[c*CV+f], w1 = Wself1[c*CV+f];
        nh0 += sa0[c]*w0;
        x += sa1[c*3+0]*w1;
        y += sa1[c*3+1]*w1;
        z += sa1[c*3+2]*w1;
    }
    // LayerNorm over channels
    float mu  = warpsum(nh0) * (1.f/32.f);
    float dv  = nh0 - mu;
    float var = warpsum(dv*dv) * (1.f/32.f);
    g_h0[n*CV+f] = dv*rsqrtf(var + 1e-5f)*gamma0[f] + beta0[f];
    // equivariant norm-gate
    float nrm  = sqrtf(x*x + y*y + z*z + 1e-12f);
    float mun  = warpsum(nrm) * (1.f/32.f);
    float dn   = nrm - mun;
    float varn = warpsum(dn*dn) * (1.f/32.f);
    float nln  = dn*rsqrtf(varn + 1e-5f)*gamma1[f];
    float sc   = nln / (nrm + 1e-8f);
    g_h1[(n*CV+f)*3+0] = x*sc;
    g_h1[(n*CV+f)*3+1] = y*sc;
    g_h1[(n*CV+f)*3+2] = z*sc;
}

// ---- K7: out = x + h1 . Wout ----
__global__ void k_final(const float* __restrict__ coords,
                        const float* __restrict__ Wout,
                        float* __restrict__ out){
    int n = blockIdx.x*blockDim.x + threadIdx.x;
    if (n >= NNODE) return;
    float dx=0, dy=0, dz=0;
    #pragma unroll 4
    for (int c = 0; c < CV; c++){
        float w = Wout[c];
        int i = (n*CV+c)*3;
        dx += g_h1[i+0]*w; dy += g_h1[i+1]*w; dz += g_h1[i+2]*w;
    }
    out[n*3+0] = coords[n*3+0] + dx;
    out[n*3+1] = coords[n*3+1] + dy;
    out[n*3+2] = coords[n*3+2] + dz;
}

extern "C" void kernel_launch(void* const* d_in, const int* in_sizes, int n_in,
                              void* d_out, int out_size){
    const float* seq    = (const float*)d_in[0];
    const float* pair   = (const float*)d_in[1];
    const float* bppm   = (const float*)d_in[2];
    const float* coords = (const float*)d_in[3];
    const int*   esrc   = (const int*)  d_in[4];
    const int*   edst   = (const int*)  d_in[5];
    const float* Win0   = (const float*)d_in[6];
    const float* Win1   = (const float*)d_in[7];
    const float* Wr1    = (const float*)d_in[8];
    const float* br1    = (const float*)d_in[9];
    const float* Wr2    = (const float*)d_in[10];
    const float* br2    = (const float*)d_in[11];
    const float* Wm00   = (const float*)d_in[12];
    const float* Wm01   = (const float*)d_in[13];
    const float* Wm10   = (const float*)d_in[14];
    const float* Wm11   = (const float*)d_in[15];
    const float* Wq     = (const float*)d_in[16];
    const float* Wself0 = (const float*)d_in[17];
    const float* Wself1 = (const float*)d_in[18];
    const float* gamma0 = (const float*)d_in[19];
    const float* beta0  = (const float*)d_in[20];
    const float* gamma1 = (const float*)d_in[21];
    const float* Wout   = (const float*)d_in[22];

    int E = in_sizes[4];
    if (E > EMAX) E = EMAX;   // safety (never expected)

    cudaFuncSetAttribute(k_edge_pass1,
                         cudaFuncAttributeMaxDynamicSharedMemorySize, SMEM_BYTES);

    k_init_nodes<<<NNODE, 128>>>(seq, coords, Win0, Win1);
    k_edge_setup<<<(E+7)/8, 256>>>(coords, pair, bppm, esrc, edst, E);

    for (int l = 0; l < NLV; l++){
        k_layer_zero<<<(NNODE*CV*3 + 255)/256, 256>>>();
        k_node_pre<<<NNODE, 32>>>(Wq + l*CV*CV, Wm00 + l*CV*CV, Wm10 + l*CV*CV,
                                  Wm01 + l*CV*CV, Wm11 + l*CV*CV);
        k_edge_pass1<<<296, 256, SMEM_BYTES>>>(esrc, edst,
                                               Wr1 + l*RADIN*HIDV, br1 + l*HIDV,
                                               Wr2 + l*HIDV*R4C,  br2 + l*R4C, E);
        k_att_norm<<<(E*HV + 255)/256, 256>>>(edst, E);
        k_edge_pass3<<<(E+7)/8, 256>>>(esrc, edst, E);
        k_node_update<<<NNODE, 32>>>(Wself0 + l*CV*CV, Wself1 + l*CV*CV,
                                     gamma0 + l*CV, beta0 + l*CV, gamma1 + l*CV);
    }
    k_final<<<(NNODE+255)/256, 256>>>(coords, Wout, (float*)d_out);
}